// round 8
// baseline (speedup 1.0000x reference)
#include <cuda_runtime.h>
#include <cuda_bf16.h>

#define BATCH 4096
#define TT    1024
#define NVOC  32000
#define HID   16

typedef unsigned long long ull;

// Scratch (device globals: allocation-free rule)
__device__ float g_xtab[NVOC * HID];   // 2MB: precomputed x-projection per token
__device__ float g_hfin[BATCH * HID];  // 256KB: final hidden states

// ---- packed f32x2 helpers on 64-bit registers ----
__device__ __forceinline__ ull ffma2(ull a, ull b, ull c) {
    ull d;
    asm("fma.rn.f32x2 %0, %1, %2, %3;" : "=l"(d) : "l"(a), "l"(b), "l"(c));
    return d;
}
__device__ __forceinline__ ull add2(ull a, ull b) {
    ull d;
    asm("add.rn.f32x2 %0, %1, %2;" : "=l"(d) : "l"(a), "l"(b));
    return d;
}
__device__ __forceinline__ ull pk(float lo, float hi) {
    ull r;
    asm("mov.b64 %0, {%1, %2};" : "=l"(r) : "f"(lo), "f"(hi));
    return r;
}
__device__ __forceinline__ float hsum2(ull a) {   // lo + hi
    float lo, hi;
    asm("mov.b64 {%0, %1}, %2;" : "=f"(lo), "=f"(hi) : "l"(a));
    return lo + hi;
}
__device__ __forceinline__ float tanhx(float x) {
    float r;
    asm("tanh.approx.f32 %0, %1;" : "=f"(r) : "f"(x));
    return r;
}
__device__ __forceinline__ unsigned smem_u32(const void* p) {
    unsigned a;
    asm("{ .reg .u64 t; cvta.to.shared.u64 t, %1; cvt.u32.u64 %0, t; }"
        : "=r"(a) : "l"(p));
    return a;
}

// ---------------------------------------------------------------------------
// Kernel 1: xtab[v][o] = Wx_b[o] + sum_h embed[v][h] * Wx_w[o][h]
// ---------------------------------------------------------------------------
__global__ void build_xtab(const float* __restrict__ embed,
                           const float* __restrict__ Wxw,
                           const float* __restrict__ Wxb) {
    int tid = blockIdx.x * blockDim.x + threadIdx.x;
    if (tid >= NVOC * HID) return;
    int v = tid >> 4;
    int o = tid & 15;
    const float4* er = (const float4*)(embed + v * HID);
    const float4* wr = (const float4*)(Wxw + o * HID);
    float s = Wxb[o];
#pragma unroll
    for (int i = 0; i < 4; i++) {
        float4 e = __ldg(&er[i]);
        float4 w = __ldg(&wr[i]);
        s += e.x * w.x + e.y * w.y + e.z * w.z + e.w * w.w;
    }
    g_xtab[tid] = s;
}

// ---------------------------------------------------------------------------
// Kernel 2: recurrence (stable ~80us, unchanged). 128-thread CTAs; warp = 8
// batches; h via per-warp ping-pong SMEM (stride-20 conflict-free); token
// ring (16) feeds xtab ring (8).
// ---------------------------------------------------------------------------
__global__ void __launch_bounds__(128) rnn_scan(const int* __restrict__ seq,
                                                const float* __restrict__ Wh) {
    __shared__ float hbuf[4][2][8 * 20];
    const int lane = threadIdx.x & 31;
    const int wid  = threadIdx.x >> 5;
    const int warp = blockIdx.x * 4 + wid;
    const int bl = lane & 7;
    const int p  = lane >> 3;

    for (int i = lane; i < 8 * 20; i += 32) hbuf[wid][0][i] = 0.f;

    const unsigned sb0 = smem_u32(&hbuf[wid][0][0]) + bl * 80;
    const unsigned sb1 = smem_u32(&hbuf[wid][1][0]) + bl * 80;

    ull wh[4][8];
#pragma unroll
    for (int i = 0; i < 4; i++) {
        const float4* r = (const float4*)(Wh + (4 * p + i) * HID);
#pragma unroll
        for (int j = 0; j < 4; j++) {
            float4 t = __ldg(&r[j]);
            wh[i][2 * j]     = pk(t.x, t.y);
            wh[i][2 * j + 1] = pk(t.z, t.w);
        }
    }

    const int* myseq = seq + (warp * 8 + bl) * TT;
    const float4* xt = (const float4*)g_xtab;

    int   tokring[8];
    float4 xpring[8];
#pragma unroll
    for (int i = 0; i < 8; i++) {
        tokring[i] = __ldg(&myseq[i + 8]);
        xpring[i]  = __ldg(&xt[__ldg(&myseq[i]) * 4 + p]);
    }
    __syncwarp();

#pragma unroll 8
    for (int t = 0; t < TT; t++) {
        const int slot = t & 7;
        float4 cur = xpring[slot];
        int tok = tokring[slot];
        xpring[slot] = __ldg(&xt[tok * 4 + p]);
        int tn = t + 16; if (tn > TT - 1) tn = TT - 1;
        tokring[slot] = __ldg(&myseq[tn]);

        const unsigned rbase = (t & 1) ? sb1 : sb0;
        const unsigned wbase = (t & 1) ? sb0 : sb1;

        ull hp[8];
        asm volatile("ld.shared.v2.b64 {%0,%1},[%2];"
                     : "=l"(hp[0]), "=l"(hp[1]) : "r"(rbase) : "memory");
        asm volatile("ld.shared.v2.b64 {%0,%1},[%2];"
                     : "=l"(hp[2]), "=l"(hp[3]) : "r"(rbase + 16) : "memory");
        asm volatile("ld.shared.v2.b64 {%0,%1},[%2];"
                     : "=l"(hp[4]), "=l"(hp[5]) : "r"(rbase + 32) : "memory");
        asm volatile("ld.shared.v2.b64 {%0,%1},[%2];"
                     : "=l"(hp[6]), "=l"(hp[7]) : "r"(rbase + 48) : "memory");

        ull aL0 = ffma2(wh[0][0], hp[0], pk(cur.x, 0.f));
        ull aL1 = ffma2(wh[1][0], hp[0], pk(cur.y, 0.f));
        ull aL2 = ffma2(wh[2][0], hp[0], pk(cur.z, 0.f));
        ull aL3 = ffma2(wh[3][0], hp[0], pk(cur.w, 0.f));
        ull aH0 = ffma2(wh[0][4], hp[4], 0ull);
        ull aH1 = ffma2(wh[1][4], hp[4], 0ull);
        ull aH2 = ffma2(wh[2][4], hp[4], 0ull);
        ull aH3 = ffma2(wh[3][4], hp[4], 0ull);
#pragma unroll
        for (int q = 1; q < 4; q++) {
            aL0 = ffma2(wh[0][q], hp[q], aL0);
            aL1 = ffma2(wh[1][q], hp[q], aL1);
            aL2 = ffma2(wh[2][q], hp[q], aL2);
            aL3 = ffma2(wh[3][q], hp[q], aL3);
            aH0 = ffma2(wh[0][q + 4], hp[q + 4], aH0);
            aH1 = ffma2(wh[1][q + 4], hp[q + 4], aH1);
            aH2 = ffma2(wh[2][q + 4], hp[q + 4], aH2);
            aH3 = ffma2(wh[3][q + 4], hp[q + 4], aH3);
        }
        float h0 = tanhx(hsum2(add2(aL0, aH0)));
        float h1 = tanhx(hsum2(add2(aL1, aH1)));
        float h2 = tanhx(hsum2(add2(aL2, aH2)));
        float h3 = tanhx(hsum2(add2(aL3, aH3)));

        asm volatile("st.shared.v4.b32 [%0],{%1,%2,%3,%4};"
                     :: "r"(wbase + 16 * p), "f"(h0), "f"(h1), "f"(h2), "f"(h3)
                     : "memory");
        __syncwarp();
    }

    float4 hf = *(const float4*)&hbuf[wid][0][bl * 20 + 4 * p];
    int b = warp * 8 + bl;
    *(float4*)(g_hfin + b * HID + 4 * p) = hf;
}

// ---------------------------------------------------------------------------
// Kernel 3: out[b][v] = out_b[v] + sum_h hfin[b][h] * out_w[v][h]
// R8: pack along v (output dim). Lane computes 4 outputs as 2 packed f32x2
// accumulators over 16 broadcast h values. h staged DUPLICATED in SMEM
// (pk(h,h), 128B/batch) so operands feed FFMA2 directly. Zero finish math:
// accumulators ARE the packed result -> direct STG.128.
// Block = (128-v tile) x (256 batches); 4 warps x 64 batches; grid 4000.
// ---------------------------------------------------------------------------
#define OB_BATCH 256
__global__ void __launch_bounds__(128) out_proj(const float* __restrict__ outw,
                                                const float* __restrict__ outb,
                                                float* __restrict__ out) {
    __shared__ ull s_h[OB_BATCH * 16];          // duplicated h pairs, 32KB
    const int tid  = threadIdx.x;
    const int lane = tid & 31;
    const int wid  = tid >> 5;                  // 0..3
    const int vgrp = blockIdx.x % 250;
    const int bgrp = blockIdx.x / 250;          // 0..15
    const int v0 = vgrp * 128 + lane * 4;
    const int b0 = bgrp * OB_BATCH;

    // stage h duplicated: s_h[b*16 + h] = pk(h_val, h_val)
    {
        const float* src = g_hfin + (size_t)b0 * HID;
#pragma unroll 8
        for (int i = tid; i < OB_BATCH * 16; i += 128) {
            float v = __ldg(&src[i]);
            s_h[i] = pk(v, v);
        }
    }

    // weight tile transposed into v-pairs: w2[h][0]=(v0,v0+1), w2[h][1]=(v0+2,v0+3)
    ull w2[16][2];
    {
        float r[4][16];
#pragma unroll
        for (int i = 0; i < 4; i++) {
            const float4* rr = (const float4*)(outw + (v0 + i) * HID);
#pragma unroll
            for (int j = 0; j < 4; j++) {
                float4 t = __ldg(&rr[j]);
                r[i][4 * j] = t.x; r[i][4 * j + 1] = t.y;
                r[i][4 * j + 2] = t.z; r[i][4 * j + 3] = t.w;
            }
        }
#pragma unroll
        for (int h = 0; h < 16; h++) {
            w2[h][0] = pk(r[0][h], r[1][h]);
            w2[h][1] = pk(r[2][h], r[3][h]);
        }
    }
    float4 ob = __ldg((const float4*)(outb + v0));
    const ull bias01 = pk(ob.x, ob.y);
    const ull bias23 = pk(ob.z, ob.w);
    __syncthreads();

    const int bcnt = OB_BATCH / 4;              // 64 per warp
    unsigned haddr = smem_u32(s_h) + (unsigned)(wid * bcnt) * 128;  // 128B/batch
    float* dst = out + (size_t)(b0 + wid * bcnt) * NVOC + v0;

#pragma unroll 2
    for (int i = 0; i < bcnt; i++) {
        // broadcast LDS of 16 duplicated h pairs (128B)
        ull hp[16];
#pragma unroll
        for (int q = 0; q < 8; q++) {
            asm volatile("ld.shared.v2.b64 {%0,%1},[%2];"
                         : "=l"(hp[2 * q]), "=l"(hp[2 * q + 1])
                         : "r"(haddr + 16 * q));
        }

        // 2 packed accumulators x two 8-deep chains
        ull a0A = ffma2(w2[0][0], hp[0], bias01);
        ull a1A = ffma2(w2[0][1], hp[0], bias23);
        ull a0B = ffma2(w2[8][0], hp[8], 0ull);
        ull a1B = ffma2(w2[8][1], hp[8], 0ull);
#pragma unroll
        for (int h = 1; h < 8; h++) {
            a0A = ffma2(w2[h][0], hp[h], a0A);
            a1A = ffma2(w2[h][1], hp[h], a1A);
            a0B = ffma2(w2[h + 8][0], hp[h + 8], a0B);
            a1B = ffma2(w2[h + 8][1], hp[h + 8], a1B);
        }
        ull r01 = add2(a0A, a0B);
        ull r23 = add2(a1A, a1B);

        asm volatile("st.global.cs.v2.b64 [%0],{%1,%2};"
                     :: "l"(dst), "l"(r01), "l"(r23) : "memory");

        haddr += 128;
        dst += NVOC;
    }
}

// ---------------------------------------------------------------------------
extern "C" void kernel_launch(void* const* d_in, const int* in_sizes, int n_in,
                              void* d_out, int out_size) {
    const int*   seq   = (const int*)d_in[0];
    const float* embed = (const float*)d_in[1];
    const float* Wh    = (const float*)d_in[2];
    const float* Wxw   = (const float*)d_in[3];
    const float* Wxb   = (const float*)d_in[4];
    const float* outw  = (const float*)d_in[5];
    const float* outb  = (const float*)d_in[6];
    float* out = (float*)d_out;

    build_xtab<<<(NVOC * HID + 255) / 256, 256>>>(embed, Wxw, Wxb);
    rnn_scan<<<BATCH / 32, 128>>>(seq, Wh);
    out_proj<<<250 * (BATCH / OB_BATCH), 128>>>(outw, outb, out);  // 4000 blocks
}